// round 2
// baseline (speedup 1.0000x reference)
#include <cuda_runtime.h>
#include <cuda_bf16.h>

#define GEPS 1e-8f
constexpr int BS = 256;

__global__ __launch_bounds__(BS) void gaussians_cov_kernel(
    const float4* __restrict__ q,     // [N] float4 (w,x,y,z)
    const float*  __restrict__ s,     // [N*3]
    float*        __restrict__ out,   // [N*9]
    int N)
{
    __shared__ float ssm[BS * 3];   // staged scales
    __shared__ float osm[BS * 9];   // staged outputs

    const int base = blockIdx.x * BS;
    const int tid  = threadIdx.x;
    const bool full = (base + BS) <= N;

    if (full) {
        // ---- cooperative coalesced load of scales (float4) ----
        // base*3 floats offset: 768*blockIdx -> 16B aligned.
        const float4* s4   = reinterpret_cast<const float4*>(s) + (size_t)base * 3 / 4;
        float4*       ssm4 = reinterpret_cast<float4*>(ssm);
        if (tid < BS * 3 / 4) ssm4[tid] = s4[tid];
        __syncthreads();

        // ---- per-thread compute ----
        float4 qv = q[base + tid];
        float w = qv.x, x = qv.y, y = qv.z, z = qv.w;
        float inv = rsqrtf(w * w + x * x + y * y + z * z);
        w *= inv; x *= inv; y *= inv; z *= inv;

        const float r00 = 1.f - 2.f * (y * y + z * z);
        const float r01 = 2.f * (x * y - w * z);
        const float r02 = 2.f * (x * z + w * y);
        const float r10 = 2.f * (x * y + w * z);
        const float r11 = 1.f - 2.f * (x * x + z * z);
        const float r12 = 2.f * (y * z - w * x);
        const float r20 = 2.f * (x * z - w * y);
        const float r21 = 2.f * (y * z + w * x);
        const float r22 = 1.f - 2.f * (x * x + y * y);

        float sa = fabsf(ssm[tid * 3 + 0]) + GEPS;
        float sb = fabsf(ssm[tid * 3 + 1]) + GEPS;
        float sc = fabsf(ssm[tid * 3 + 2]) + GEPS;
        const float a = sa * sa, b = sb * sb, c = sc * sc;

        // Sigma = R diag(a,b,c) R^T  (symmetric: 6 unique terms)
        const float m00 = r00 * r00 * a + r01 * r01 * b + r02 * r02 * c;
        const float m01 = r00 * r10 * a + r01 * r11 * b + r02 * r12 * c;
        const float m02 = r00 * r20 * a + r01 * r21 * b + r02 * r22 * c;
        const float m11 = r10 * r10 * a + r11 * r11 * b + r12 * r12 * c;
        const float m12 = r10 * r20 * a + r11 * r21 * b + r12 * r22 * c;
        const float m22 = r20 * r20 * a + r21 * r21 * b + r22 * r22 * c;

        // stride-9 smem writes: 9 coprime with 32 -> conflict-free
        float* o = osm + tid * 9;
        o[0] = m00; o[1] = m01; o[2] = m02;
        o[3] = m01; o[4] = m11; o[5] = m12;
        o[6] = m02; o[7] = m12; o[8] = m22;
        __syncthreads();

        // ---- cooperative coalesced store (float4) ----
        // base*9 floats offset: 2304*blockIdx -> 16B aligned.
        float4*       out4 = reinterpret_cast<float4*>(out) + (size_t)base * 9 / 4;
        const float4* osm4 = reinterpret_cast<const float4*>(osm);
        #pragma unroll
        for (int i = tid; i < BS * 9 / 4; i += BS) out4[i] = osm4[i];
    } else {
        // tail block: scalar guarded path (uniform branch per block)
        const int n = base + tid;
        if (n < N) {
            float4 qv = q[n];
            float w = qv.x, x = qv.y, y = qv.z, z = qv.w;
            float inv = rsqrtf(w * w + x * x + y * y + z * z);
            w *= inv; x *= inv; y *= inv; z *= inv;

            const float r00 = 1.f - 2.f * (y * y + z * z);
            const float r01 = 2.f * (x * y - w * z);
            const float r02 = 2.f * (x * z + w * y);
            const float r10 = 2.f * (x * y + w * z);
            const float r11 = 1.f - 2.f * (x * x + z * z);
            const float r12 = 2.f * (y * z - w * x);
            const float r20 = 2.f * (x * z - w * y);
            const float r21 = 2.f * (y * z + w * x);
            const float r22 = 1.f - 2.f * (x * x + y * y);

            float sa = fabsf(s[n * 3 + 0]) + GEPS;
            float sb = fabsf(s[n * 3 + 1]) + GEPS;
            float sc = fabsf(s[n * 3 + 2]) + GEPS;
            const float a = sa * sa, b = sb * sb, c = sc * sc;

            float* o = out + (size_t)n * 9;
            o[0] = r00 * r00 * a + r01 * r01 * b + r02 * r02 * c;
            o[1] = r00 * r10 * a + r01 * r11 * b + r02 * r12 * c;
            o[2] = r00 * r20 * a + r01 * r21 * b + r02 * r22 * c;
            o[3] = o[1];
            o[4] = r10 * r10 * a + r11 * r11 * b + r12 * r12 * c;
            o[5] = r10 * r20 * a + r11 * r21 * b + r12 * r22 * c;
            o[6] = o[2];
            o[7] = o[5];
            o[8] = r20 * r20 * a + r21 * r21 * b + r22 * r22 * c;
        }
    }
}

extern "C" void kernel_launch(void* const* d_in, const int* in_sizes, int n_in,
                              void* d_out, int out_size) {
    const float4* q = (const float4*)d_in[0];   // quaternion [N,4]
    const float*  s = (const float*)d_in[1];    // scale [N,3]
    float* out = (float*)d_out;                 // [N,3,3]
    const int N = in_sizes[0] / 4;

    const int grid = (N + BS - 1) / BS;
    gaussians_cov_kernel<<<grid, BS>>>(q, s, out, N);
}